// round 8
// baseline (speedup 1.0000x reference)
#include <cuda_runtime.h>
#include <cuda_bf16.h>
#include <cstdint>

// Problem constants
#define B_    64
#define N_    128
#define LVLS  3
#define NT    32
#define TL    32
#define H_    256
#define OUT_  10
#define BC    4              // batch chunks
#define MB    16             // batch rows per chunk
#define NP    8              // batch-row pairs per chunk
#define NJOBS (LVLS*NT*BC)   // 384

// W staging pipeline
#define STG_K4   4                         // k4 chunks per stage
#define NSTAGE   16                        // stages per step (64 k4)
#define NSLOT    3                         // smem ring slots
#define STG_BYTES (STG_K4 * 1024 * 16)     // 65536 B per stage

// Dynamic smem layout (bytes)
#define SM_W     0
#define SM_HP    (NSLOT * STG_BYTES)                    // 196608
#define SM_SBF   (SM_HP + NP * H_ * 8)                  // +16384 = 212992
#define SM_TAIL  (SM_SBF + NP * N_ * 8)                 // +8192  = 221184
#define SM_TOTAL (SM_TAIL + 256)                        // 221440

// Device-global scratch (allocation-free)
__device__ float  g_v[LVLS * 1024];
__device__ float  g_u[LVLS * 1024];
__device__ float4 g_Wt4[LVLS * 64 * 1024];   // [l][k4][row] = W_hh[l][row][4k4..+3]
__device__ float  g_partial[NJOBS * MB * OUT_];
__device__ int    g_order[NJOBS];
__device__ int    g_ticket;

// ---- packed f32x2 helpers (sm_100+) --------------------------------------
__device__ __forceinline__ unsigned long long pack2(float lo, float hi) {
    unsigned long long r;
    asm("mov.b64 %0, {%1, %2};" : "=l"(r) : "f"(lo), "f"(hi));
    return r;
}
__device__ __forceinline__ void unpack2(unsigned long long v, float& lo, float& hi) {
    asm("mov.b64 {%0, %1}, %2;" : "=f"(lo), "=f"(hi) : "l"(v));
}
__device__ __forceinline__ unsigned long long ffma2(unsigned long long a,
                                                    unsigned long long b,
                                                    unsigned long long c) {
    unsigned long long d;
    asm("fma.rn.f32x2 %0, %1, %2, %3;" : "=l"(d) : "l"(a), "l"(b), "l"(c));
    return d;
}
__device__ __forceinline__ void cp16(uint32_t dst, const void* src) {
    asm volatile("cp.async.cg.shared.global [%0], [%1], 16;"
                 :: "r"(dst), "l"(src) : "memory");
}
__device__ __forceinline__ void cp_commit() {
    asm volatile("cp.async.commit_group;" ::: "memory");
}
template <int N>
__device__ __forceinline__ void cp_wait() {
    asm volatile("cp.async.wait_group %0;" :: "n"(N) : "memory");
}

__device__ __forceinline__ float fast_sig(float x) {
    return __fdividef(1.0f, 1.0f + __expf(-x));
}
__device__ __forceinline__ float fast_tanh(float x) {
    float s = __fdividef(1.0f, 1.0f + __expf(-2.0f * x));
    return fmaf(2.0f, s, -1.0f);
}

// ---------------------------------------------------------------------------
// prep: v = W_ih@w_enc, u = W_ih@b_enc + b_ih + b_hh; transpose W_hh into
// g_Wt4 (coalesced-by-row layout). One thread per global gate row (3072).
// ---------------------------------------------------------------------------
__global__ void prep_kernel(const float* __restrict__ W_ih,
                            const float* __restrict__ W_enc,
                            const float* __restrict__ b_enc,
                            const float* __restrict__ b_ih,
                            const float* __restrict__ b_hh,
                            const float* __restrict__ W_hh) {
    __shared__ float we[H_];
    __shared__ float be[H_];
    int tid = threadIdx.x;
    we[tid] = W_enc[tid];
    be[tid] = b_enc[tid];
    __syncthreads();

    int r   = blockIdx.x * 256 + tid;   // 0..3071
    int l   = r >> 10;
    int row = r & 1023;
    const float4* Wr = reinterpret_cast<const float4*>(W_ih + (size_t)r * H_);
    const float4* Hr = reinterpret_cast<const float4*>(W_hh + (size_t)r * H_);
    float4* dst = g_Wt4 + (((size_t)l) << 16) + row;

    float sv = 0.f, su = 0.f;
#pragma unroll 4
    for (int k4 = 0; k4 < 64; k4++) {
        float4 w = __ldg(Wr + k4);
        int k = 4 * k4;
        sv = fmaf(w.x, we[k + 0], sv); sv = fmaf(w.y, we[k + 1], sv);
        sv = fmaf(w.z, we[k + 2], sv); sv = fmaf(w.w, we[k + 3], sv);
        su = fmaf(w.x, be[k + 0], su); su = fmaf(w.y, be[k + 1], su);
        su = fmaf(w.z, be[k + 2], su); su = fmaf(w.w, be[k + 3], su);
        dst[k4 << 10] = __ldg(Hr + k4);
    }
    g_v[r] = sv;
    g_u[r] = su + b_ih[r] + b_hh[r];
}

// ---------------------------------------------------------------------------
// order: rank jobs by descending trunk length (LPT) + ticket reset.
// ---------------------------------------------------------------------------
__global__ void order_kernel(const int* __restrict__ trunk_len) {
    __shared__ int len_s[NJOBS];
    int i = threadIdx.x;               // 0..383
    int l = i >> 7;
    int t = (i >> 2) & 31;
    int L = trunk_len[l * NT + t];
    L = min(max(L, 1), TL);
    len_s[i] = L;
    __syncthreads();
    int Li = len_s[i];
    int rank = 0;
    for (int k = 0; k < NJOBS; k++) {
        int Lk = len_s[k];
        rank += (Lk > Li) || (Lk == Li && k < i);
    }
    g_order[rank] = i;
    if (i == 0) g_ticket = 0;
}

// ---------------------------------------------------------------------------
// Main LSTM: 512-thread persistent CTAs, LPT ticket dispatch.
// W_hh streams L2 -> SMEM via a 3-slot cp.async ring (2 stages in flight);
// consumption is broadcast LDS + packed fma.rn.f32x2.
// Thread (j = tid&255, h = tid>>8) owns gate rows {j,j+256,j+512,j+768}
// for row-pairs [4h, 4h+4).
// ---------------------------------------------------------------------------
__global__ void __launch_bounds__(512, 1)
lstm_kernel(const float* __restrict__ bf,
            const int*   __restrict__ trunk_idx,
            const int*   __restrict__ trunk_len,
            const float* __restrict__ W_lin) {
    extern __shared__ char smem[];
    float4* sW   = reinterpret_cast<float4*>(smem + SM_W);
    float2* hp   = reinterpret_cast<float2*>(smem + SM_HP);    // [NP][H_]
    float2* sbf2 = reinterpret_cast<float2*>(smem + SM_SBF);   // [NP][N_]
    int*    tail = reinterpret_cast<int*>(smem + SM_TAIL);
    int*    idx_s = tail;            // [TL]
    // tail[32] = job, tail[33] = len

    const int tid = threadIdx.x;
    const int j   = tid & 255;
    const int h   = tid >> 8;

    const uint32_t sW_u32 =
        (uint32_t)__cvta_generic_to_shared(smem) + (uint32_t)SM_W;

    for (;;) {
        if (tid == 0) {
            int tk = atomicAdd(&g_ticket, 1);
            tail[32] = (tk < NJOBS) ? g_order[tk] : -1;
        }
        // Drain previous job's in-flight copies before slot reuse.
        cp_wait<0>();
        __syncthreads();
        const int job = tail[32];
        if (job < 0) break;

        const int l  = job >> 7;
        const int t  = (job >> 2) & 31;
        const int bc = job & 3;

        const char* gW = reinterpret_cast<const char*>(g_Wt4 + (((size_t)l) << 16));

        // Prologue: issue stages 0 and 1.
        {
            const char* src0 = gW + 0 * STG_BYTES + tid * 128;
            uint32_t    dst0 = sW_u32 + 0 * STG_BYTES + tid * 128;
#pragma unroll
            for (int c = 0; c < 8; c++) cp16(dst0 + 16 * c, src0 + 16 * c);
            cp_commit();
            const char* src1 = gW + 1 * STG_BYTES + tid * 128;
            uint32_t    dst1 = sW_u32 + 1 * STG_BYTES + tid * 128;
#pragma unroll
            for (int c = 0; c < 8; c++) cp16(dst1 + 16 * c, src1 + 16 * c);
            cp_commit();
        }
        int issued = 2;   // stages issued since job start

        // Per-job loads
        float vj[4], uj[4];
#pragma unroll
        for (int g = 0; g < 4; g++) {
            vj[g] = g_v[l * 1024 + (g << 8) + j];
            uj[g] = g_u[l * 1024 + (g << 8) + j];
        }
        for (int i = tid; i < NP * N_; i += 512) {
            int p = i >> 7, n = i & 127;
            int row0 = bc * MB + 2 * p;
            sbf2[p * N_ + n] = make_float2(bf[row0 * N_ + n], bf[(row0 + 1) * N_ + n]);
        }
        if (tid < TL) idx_s[tid] = trunk_idx[(l * NT + t) * TL + tid];
        if (tid == 0) {
            int L = trunk_len[l * NT + t];
            tail[33] = min(max(L, 1), TL);
        }
        for (int i = tid; i < NP * H_; i += 512)
            hp[i] = make_float2(0.f, 0.f);
        __syncthreads();

        const int len = tail[33];
        float c[8];
#pragma unroll
        for (int m = 0; m < 8; m++) c[m] = 0.f;

        int q = 0;   // consume counter (slot = q % 3)

        for (int step = 0; step < len; step++) {
            const int n = idx_s[step];

            unsigned long long acc[4][4];   // [gate][pair-in-half]
#pragma unroll
            for (int pp = 0; pp < 4; pp++) {
                float2 s2 = sbf2[(4 * h + pp) * N_ + n];
#pragma unroll
                for (int g = 0; g < 4; g++)
                    acc[g][pp] = pack2(fmaf(s2.x, vj[g], uj[g]),
                                       fmaf(s2.y, vj[g], uj[g]));
            }

            for (int it = 0; it < NSTAGE; it++) {
                cp_wait<1>();        // stage q landed
                __syncthreads();     // visible to all; prior slot fully consumed

                // Issue the stage 2 ahead (slot (q+2)%3 was consumed at q-1).
                {
                    int st  = issued & (NSTAGE - 1);
                    int sl  = issued % NSLOT;
                    const char* src = gW + (size_t)st * STG_BYTES + tid * 128;
                    uint32_t    dst = sW_u32 + sl * STG_BYTES + tid * 128;
#pragma unroll
                    for (int cc = 0; cc < 8; cc++) cp16(dst + 16 * cc, src + 16 * cc);
                    cp_commit();
                    issued++;
                }

                const int slot = q % NSLOT;
                const float4* Ws = sW + (size_t)slot * (STG_K4 * 1024);
#pragma unroll
                for (int i = 0; i < STG_K4; i++) {
                    const int k4 = (q & (NSTAGE - 1)) * STG_K4 + i;
                    const float4* Wb = Ws + i * 1024;
#pragma unroll
                    for (int gh = 0; gh < 2; gh++) {
                        const float4 wa = Wb[(2 * gh) * 256 + j];
                        const float4 wb = Wb[(2 * gh + 1) * 256 + j];
                        unsigned long long wpa0 = pack2(wa.x, wa.x);
                        unsigned long long wpa1 = pack2(wa.y, wa.y);
                        unsigned long long wpa2 = pack2(wa.z, wa.z);
                        unsigned long long wpa3 = pack2(wa.w, wa.w);
                        unsigned long long wpb0 = pack2(wb.x, wb.x);
                        unsigned long long wpb1 = pack2(wb.y, wb.y);
                        unsigned long long wpb2 = pack2(wb.z, wb.z);
                        unsigned long long wpb3 = pack2(wb.w, wb.w);
#pragma unroll
                        for (int pp = 0; pp < 4; pp++) {
                            const int p = 4 * h + pp;
                            const ulonglong2 qa = *reinterpret_cast<const ulonglong2*>(
                                &hp[p * H_ + k4 * 4]);
                            const ulonglong2 qb = *reinterpret_cast<const ulonglong2*>(
                                &hp[p * H_ + k4 * 4 + 2]);
                            unsigned long long A  = acc[2 * gh][pp];
                            unsigned long long Bq = acc[2 * gh + 1][pp];
                            A  = ffma2(qa.x, wpa0, A);
                            A  = ffma2(qa.y, wpa1, A);
                            A  = ffma2(qb.x, wpa2, A);
                            A  = ffma2(qb.y, wpa3, A);
                            Bq = ffma2(qa.x, wpb0, Bq);
                            Bq = ffma2(qa.y, wpb1, Bq);
                            Bq = ffma2(qb.x, wpb2, Bq);
                            Bq = ffma2(qb.y, wpb3, Bq);
                            acc[2 * gh][pp]     = A;
                            acc[2 * gh + 1][pp] = Bq;
                        }
                    }
                }
                q++;
            }

            __syncthreads();   // all hp reads done before overwrite
#pragma unroll
            for (int pp = 0; pp < 4; pp++) {
                const int p = 4 * h + pp;
                float i0, i1, f0, f1, g0, g1, o0, o1;
                unpack2(acc[0][pp], i0, i1);
                unpack2(acc[1][pp], f0, f1);
                unpack2(acc[2][pp], g0, g1);
                unpack2(acc[3][pp], o0, o1);
                float c0 = fmaf(fast_sig(f0), c[2 * pp],     fast_sig(i0) * fast_tanh(g0));
                float c1 = fmaf(fast_sig(f1), c[2 * pp + 1], fast_sig(i1) * fast_tanh(g1));
                c[2 * pp] = c0; c[2 * pp + 1] = c1;
                hp[p * H_ + j] = make_float2(fast_sig(o0) * fast_tanh(c0),
                                             fast_sig(o1) * fast_tanh(c1));
            }
            __syncthreads();
        }

        // ---- epilogue: partial[m][o] = h_last[m] @ W_lin[l][:,o] ----
        if (h == 0 && j < MB * OUT_) {
            int m = j / OUT_;
            int o = j - m * OUT_;
            int p = m >> 1;
            int hi = m & 1;
            const float* Wl = W_lin + (size_t)l * H_ * OUT_ + o;
            float s = 0.f;
#pragma unroll 8
            for (int d = 0; d < H_; d++) {
                float2 hv2 = hp[p * H_ + d];
                float hv = hi ? hv2.y : hv2.x;
                s = fmaf(hv, __ldg(Wl + d * OUT_), s);
            }
            g_partial[(job * MB + m) * OUT_ + o] = s;
        }
        __syncthreads();   // protect shared state before next job
    }
    cp_wait<0>();   // drain before exit
}

// ---------------------------------------------------------------------------
// Deterministic final reduction over trunks and levels (+ b_lin per level).
// ---------------------------------------------------------------------------
__global__ void reduce_kernel(const float* __restrict__ b_lin,
                              float* __restrict__ out) {
    int i = blockIdx.x * blockDim.x + threadIdx.x;
    if (i >= B_ * OUT_) return;
    int b  = i / OUT_;
    int o  = i % OUT_;
    int bc = b / MB;
    int m  = b % MB;
    float s = 0.f;
#pragma unroll
    for (int l = 0; l < LVLS; l++) {
        s += b_lin[l * OUT_ + o];
        for (int t = 0; t < NT; t++) {
            int job = (l * NT + t) * BC + bc;
            s += g_partial[(job * MB + m) * OUT_ + o];
        }
    }
    out[i] = s;
}

// ---------------------------------------------------------------------------
extern "C" void kernel_launch(void* const* d_in, const int* in_sizes, int n_in,
                              void* d_out, int out_size) {
    const float* batch_feature = (const float*)d_in[0];
    const int*   trunk_idx     = (const int*)  d_in[1];
    const int*   trunk_len     = (const int*)  d_in[2];
    const float* W_enc         = (const float*)d_in[3];
    const float* b_enc         = (const float*)d_in[4];
    const float* W_ih          = (const float*)d_in[5];
    const float* W_hh          = (const float*)d_in[6];
    const float* b_ih          = (const float*)d_in[7];
    const float* b_hh          = (const float*)d_in[8];
    const float* W_lin         = (const float*)d_in[9];
    const float* b_lin         = (const float*)d_in[10];
    float* out = (float*)d_out;

    cudaFuncSetAttribute(lstm_kernel,
                         cudaFuncAttributeMaxDynamicSharedMemorySize, SM_TOTAL);

    prep_kernel<<<12, 256>>>(W_ih, W_enc, b_enc, b_ih, b_hh, W_hh);
    order_kernel<<<1, NJOBS>>>(trunk_len);
    lstm_kernel<<<NJOBS, 512, SM_TOTAL>>>(batch_feature, trunk_idx, trunk_len, W_lin);
    reduce_kernel<<<(B_ * OUT_ + 127) / 128, 128>>>(b_lin, out);
}

// round 9
// speedup vs baseline: 1.7055x; 1.7055x over previous
#include <cuda_runtime.h>
#include <cuda_bf16.h>
#include <cstdint>

// Problem constants
#define B_    64
#define N_    128
#define LVLS  3
#define NT    32
#define TL    32
#define H_    256
#define OUT_  10
#define BC    4              // batch chunks
#define MB    16             // batch rows per chunk
#define NJOBS (LVLS*NT*BC)   // 384

// Device-global scratch (allocation-free)
__device__ float  g_v[LVLS * 1024];
__device__ float  g_u[LVLS * 1024];
__device__ float4 g_Wt4[LVLS * 64 * 1024];   // [l][k4][row] = W_hh[l][row][4k4..+3]
__device__ float  g_partial[NJOBS * MB * OUT_];
__device__ int    g_order[NJOBS];
__device__ int    g_ticket;

// ---- packed f32x2 helpers (sm_100+) --------------------------------------
__device__ __forceinline__ unsigned long long pack2(float lo, float hi) {
    unsigned long long r;
    asm("mov.b64 %0, {%1, %2};" : "=l"(r) : "f"(lo), "f"(hi));
    return r;
}
__device__ __forceinline__ void unpack2(unsigned long long v, float& lo, float& hi) {
    asm("mov.b64 {%0, %1}, %2;" : "=f"(lo), "=f"(hi) : "l"(v));
}
__device__ __forceinline__ unsigned long long ffma2(unsigned long long a,
                                                    unsigned long long b,
                                                    unsigned long long c) {
    unsigned long long d;
    asm("fma.rn.f32x2 %0, %1, %2, %3;" : "=l"(d) : "l"(a), "l"(b), "l"(c));
    return d;
}

__device__ __forceinline__ float fast_sig(float x) {
    return __fdividef(1.0f, 1.0f + __expf(-x));
}
__device__ __forceinline__ float fast_tanh(float x) {
    float s = __fdividef(1.0f, 1.0f + __expf(-2.0f * x));
    return fmaf(2.0f, s, -1.0f);
}

// ---------------------------------------------------------------------------
// prep: v = W_ih@w_enc, u = W_ih@b_enc + b_ih + b_hh; transpose W_hh into
// g_Wt4 (coalesced-by-row layout). One thread per global gate row (3072).
// ---------------------------------------------------------------------------
__global__ void prep_kernel(const float* __restrict__ W_ih,
                            const float* __restrict__ W_enc,
                            const float* __restrict__ b_enc,
                            const float* __restrict__ b_ih,
                            const float* __restrict__ b_hh,
                            const float* __restrict__ W_hh) {
    __shared__ float we[H_];
    __shared__ float be[H_];
    int tid = threadIdx.x;
    we[tid] = W_enc[tid];
    be[tid] = b_enc[tid];
    __syncthreads();

    int r   = blockIdx.x * 256 + tid;   // 0..3071
    int l   = r >> 10;
    int row = r & 1023;
    const float4* Wr = reinterpret_cast<const float4*>(W_ih + (size_t)r * H_);
    const float4* Hr = reinterpret_cast<const float4*>(W_hh + (size_t)r * H_);
    float4* dst = g_Wt4 + (((size_t)l) << 16) + row;

    float sv = 0.f, su = 0.f;
#pragma unroll 4
    for (int k4 = 0; k4 < 64; k4++) {
        float4 w = __ldg(Wr + k4);
        int k = 4 * k4;
        sv = fmaf(w.x, we[k + 0], sv); sv = fmaf(w.y, we[k + 1], sv);
        sv = fmaf(w.z, we[k + 2], sv); sv = fmaf(w.w, we[k + 3], sv);
        su = fmaf(w.x, be[k + 0], su); su = fmaf(w.y, be[k + 1], su);
        su = fmaf(w.z, be[k + 2], su); su = fmaf(w.w, be[k + 3], su);
        dst[k4 << 10] = __ldg(Hr + k4);
    }
    g_v[r] = sv;
    g_u[r] = su + b_ih[r] + b_hh[r];
}

// ---------------------------------------------------------------------------
// order: rank jobs by descending trunk length (LPT) + ticket reset.
// ---------------------------------------------------------------------------
__global__ void order_kernel(const int* __restrict__ trunk_len) {
    __shared__ int len_s[NJOBS];
    int i = threadIdx.x;               // 0..383
    int l = i >> 7;
    int t = (i >> 2) & 31;
    int L = trunk_len[l * NT + t];
    L = min(max(L, 1), TL);
    len_s[i] = L;
    __syncthreads();
    int Li = len_s[i];
    int rank = 0;
    for (int k = 0; k < NJOBS; k++) {
        int Lk = len_s[k];
        rank += (Lk > Li) || (Lk == Li && k < i);
    }
    g_order[rank] = i;
    if (i == 0) g_ticket = 0;
}

// ---------------------------------------------------------------------------
// Main LSTM: 512-thread persistent CTAs, LPT ticket dispatch.
// k-paired FFMA2: acc[g][m] f32x2 accumulates (even-k, odd-k) partial sums.
// W float4 (consecutive k) and h float4 are used as f32x2 pairs DIRECTLY —
// no packing MOVs in the hot loop. Thread (j=tid&255, h=tid>>8) owns gate
// rows {j,j+256,j+512,j+768} for batch rows [8h, 8h+8).
// ---------------------------------------------------------------------------
__global__ void __launch_bounds__(512, 1)
lstm_kernel(const float* __restrict__ bf,
            const int*   __restrict__ trunk_idx,
            const int*   __restrict__ trunk_len,
            const float* __restrict__ W_lin) {
    const int tid = threadIdx.x;
    const int j   = tid & 255;
    const int hh  = tid >> 8;          // batch half: rows [8hh, 8hh+8)

    __shared__ float hs[MB][H_];       // hidden state, plain layout (16 KB)
    __shared__ float sbf[MB][N_];      // batch_feature rows (8 KB)
    __shared__ int   idx_s[TL];
    __shared__ int   job_s;
    __shared__ int   len_s;

    for (;;) {
        if (tid == 0) {
            int tk = atomicAdd(&g_ticket, 1);
            job_s = (tk < NJOBS) ? g_order[tk] : -1;
        }
        __syncthreads();
        const int job = job_s;
        if (job < 0) break;

        const int l  = job >> 7;
        const int t  = (job >> 2) & 31;
        const int bc = job & 3;

        float vj[4], uj[4];
#pragma unroll
        for (int g = 0; g < 4; g++) {
            vj[g] = g_v[l * 1024 + (g << 8) + j];
            uj[g] = g_u[l * 1024 + (g << 8) + j];
        }
        for (int i = tid; i < MB * N_; i += 512)
            sbf[i >> 7][i & 127] = bf[(bc * MB + (i >> 7)) * N_ + (i & 127)];
        if (tid < TL) idx_s[tid] = trunk_idx[(l * NT + t) * TL + tid];
        if (tid == 0) {
            int L = trunk_len[l * NT + t];
            len_s = min(max(L, 1), TL);
        }
        for (int i = tid; i < MB * H_; i += 512)
            hs[i >> 8][i & 255] = 0.f;
        __syncthreads();

        const int len = len_s;
        float c[8];
#pragma unroll
        for (int m = 0; m < 8; m++) c[m] = 0.f;

        const float4* Wk = g_Wt4 + (((size_t)l) << 16) + j;  // + (k4<<10) + g*256

        for (int step = 0; step < len; step++) {
            const int n = idx_s[step];

            // acc[g][m]: f32x2 = (even-k partial, odd-k partial).
            // init: lane0 = s*v + u, lane1 = 0.
            unsigned long long acc[4][8];
#pragma unroll
            for (int m = 0; m < 8; m++) {
                float s = sbf[8 * hh + m][n];
#pragma unroll
                for (int g = 0; g < 4; g++)
                    acc[g][m] = pack2(fmaf(s, vj[g], uj[g]), 0.f);
            }

            // Recurrent GEMM, two 32-k4 halves with a re-convergence barrier
            // (keeps both batch-halves' identical W reads in the L1 window).
#pragma unroll
            for (int half = 0; half < 2; half++) {
#pragma unroll 2
                for (int kk = 0; kk < 32; kk++) {
                    const int k4 = half * 32 + kk;
                    const float4* Wb = Wk + (k4 << 10);
                    const float4 w0 = __ldg(Wb);
                    const float4 w1 = __ldg(Wb + 256);
                    const float4 w2 = __ldg(Wb + 512);
                    const float4 w3 = __ldg(Wb + 768);
                    const ulonglong2 W0 = *reinterpret_cast<const ulonglong2*>(&w0);
                    const ulonglong2 W1 = *reinterpret_cast<const ulonglong2*>(&w1);
                    const ulonglong2 W2 = *reinterpret_cast<const ulonglong2*>(&w2);
                    const ulonglong2 W3 = *reinterpret_cast<const ulonglong2*>(&w3);
#pragma unroll
                    for (int m = 0; m < 8; m++) {
                        const ulonglong2 hq = *reinterpret_cast<const ulonglong2*>(
                            &hs[8 * hh + m][k4 * 4]);          // broadcast LDS.128
                        acc[0][m] = ffma2(hq.x, W0.x, acc[0][m]);
                        acc[0][m] = ffma2(hq.y, W0.y, acc[0][m]);
                        acc[1][m] = ffma2(hq.x, W1.x, acc[1][m]);
                        acc[1][m] = ffma2(hq.y, W1.y, acc[1][m]);
                        acc[2][m] = ffma2(hq.x, W2.x, acc[2][m]);
                        acc[2][m] = ffma2(hq.y, W2.y, acc[2][m]);
                        acc[3][m] = ffma2(hq.x, W3.x, acc[3][m]);
                        acc[3][m] = ffma2(hq.y, W3.y, acc[3][m]);
                    }
                }
                __syncthreads();   // half-boundary; final one guards hs overwrite
            }

            // Activations: gate = lane0 + lane1 of each f32x2 partial pair.
#pragma unroll
            for (int m = 0; m < 8; m++) {
                float i0, i1, f0, f1, g0, g1, o0, o1;
                unpack2(acc[0][m], i0, i1);
                unpack2(acc[1][m], f0, f1);
                unpack2(acc[2][m], g0, g1);
                unpack2(acc[3][m], o0, o1);
                float gi = i0 + i1, gf = f0 + f1, gg = g0 + g1, go = o0 + o1;
                float cm = fmaf(fast_sig(gf), c[m], fast_sig(gi) * fast_tanh(gg));
                c[m] = cm;
                hs[8 * hh + m][j] = fast_sig(go) * fast_tanh(cm);
            }
            __syncthreads();   // hs complete before next step's reads
        }

        // ---- epilogue: partial[m][o] = h_last[m] @ W_lin[l][:,o] ----
        if (hh == 0 && j < MB * OUT_) {
            int m = j / OUT_;
            int o = j - m * OUT_;
            const float* Wl = W_lin + (size_t)l * H_ * OUT_ + o;
            float s = 0.f;
#pragma unroll 8
            for (int d = 0; d < H_; d++)
                s = fmaf(hs[m][d], __ldg(Wl + d * OUT_), s);
            g_partial[(job * MB + m) * OUT_ + o] = s;
        }
        __syncthreads();   // protect shared state before next job
    }
}

// ---------------------------------------------------------------------------
// Deterministic final reduction over trunks and levels (+ b_lin per level).
// ---------------------------------------------------------------------------
__global__ void reduce_kernel(const float* __restrict__ b_lin,
                              float* __restrict__ out) {
    int i = blockIdx.x * blockDim.x + threadIdx.x;
    if (i >= B_ * OUT_) return;
    int b  = i / OUT_;
    int o  = i % OUT_;
    int bc = b / MB;
    int m  = b % MB;
    float s = 0.f;
#pragma unroll
    for (int l = 0; l < LVLS; l++) {
        s += b_lin[l * OUT_ + o];
        for (int t = 0; t < NT; t++) {
            int job = (l * NT + t) * BC + bc;
            s += g_partial[(job * MB + m) * OUT_ + o];
        }
    }
    out[i] = s;
}

// ---------------------------------------------------------------------------
extern "C" void kernel_launch(void* const* d_in, const int* in_sizes, int n_in,
                              void* d_out, int out_size) {
    const float* batch_feature = (const float*)d_in[0];
    const int*   trunk_idx     = (const int*)  d_in[1];
    const int*   trunk_len     = (const int*)  d_in[2];
    const float* W_enc         = (const float*)d_in[3];
    const float* b_enc         = (const float*)d_in[4];
    const float* W_ih          = (const float*)d_in[5];
    const float* W_hh          = (const float*)d_in[6];
    const float* b_ih          = (const float*)d_in[7];
    const float* b_hh          = (const float*)d_in[8];
    const float* W_lin         = (const float*)d_in[9];
    const float* b_lin         = (const float*)d_in[10];
    float* out = (float*)d_out;

    prep_kernel<<<12, 256>>>(W_ih, W_enc, b_enc, b_ih, b_hh, W_hh);
    order_kernel<<<1, NJOBS>>>(trunk_len);
    lstm_kernel<<<NJOBS, 512>>>(batch_feature, trunk_idx, trunk_len, W_lin);
    reduce_kernel<<<(B_ * OUT_ + 127) / 128, 128>>>(b_lin, out);
}